// round 9
// baseline (speedup 1.0000x reference)
#include <cuda_runtime.h>
#include <cuda_bf16.h>

#define B_DIM 64
#define J_DIM 24
#define T_DIM 2048
#define T4 (T_DIM / 4)
#define LAMBDA_VEL 0.2
#define LAMBDA_FOOT 0.1
#define CONTACT_THRESH 0.05f

#define GRID_BLOCKS 1152   // 1152*256 = 294912 threads = 9216 warps = B*J*6 rows
#define NTHREADS 256
#define CHUNKS 16          // T4 / 32 = 512/32 chunks per row

// accumulators: [0]=recon, [1]=vel, [2]=foot_loss, [3]=cw_sum  (zero-init, reset by last block)
__device__ double g_acc[4];
__device__ unsigned int g_done;

__device__ __forceinline__ float sigmoidf_fast(float x) {
    return 1.0f / (1.0f + __expf(-x));
}

__global__ void __launch_bounds__(NTHREADS) k_fused(const float* __restrict__ pred,
                                                    const float* __restrict__ target,
                                                    const float* __restrict__ jp,
                                                    float* __restrict__ out) {
    const int tid = blockIdx.x * blockDim.x + threadIdx.x;
    const int lane = threadIdx.x & 31;
    const int wrow = tid >> 5;                 // one warp per T-row: 0..9215

    // ---------------- main: recon + vel; warp-per-row, zero scalar reloads ----------------
    float recon = 0.0f, vel = 0.0f;
    {
        const float4* p4 = (const float4*)pred;
        const float4* t4 = (const float4*)target;
        const int base = wrow * T4 + lane;     // float4 index of lane's first chunk element

        float prev31 = 0.0f;                   // lane31 carry: d3 of previous chunk

        #pragma unroll 2
        for (int k = 0; k < CHUNKS; k++) {
            int i = base + k * 32;
            float4 p = __ldcs(p4 + i);
            float4 t = __ldcs(t4 + i);
            float d0 = p.x - t.x, d1 = p.y - t.y, d2 = p.z - t.z, d3 = p.w - t.w;
            recon += d0 * d0 + d1 * d1 + d2 * d2 + d3 * d3;
            float v01 = d1 - d0, v12 = d2 - d1, v23 = d3 - d2;
            float v = v01 * v01 + v12 * v12 + v23 * v23;

            float dn = __shfl_down_sync(0xFFFFFFFFu, d0, 1);   // lanes 0-30: neighbor in-chunk
            float b0 = __shfl_sync(0xFFFFFFFFu, d0, 0);        // lane0's d0: prev chunk's missing neighbor

            if (lane < 31) {
                float v3n = dn - d3;
                v += v3n * v3n;
            } else {
                if (k > 0) {
                    float vx = b0 - prev31;                     // cross-chunk term
                    v += vx * vx;
                }
                prev31 = d3;
            }
            vel += v;
            // k == CHUNKS-1, lane 31: row end -> no term (correct: T-1 diffs per row)
        }
    }

    // ---------------- foot contact loss (unchanged from R8) ----------------
    float lsum = 0.0f, csum = 0.0f;
    {
        const int foot_map[4] = {7, 8, 10, 11};
        const int nfoot = B_DIM * 4 * T4;                 // 131072 < total threads
        if (tid < nfoot) {
            int c4 = tid & (T4 - 1);
            int row = tid >> 9;
            int b = row >> 2;
            int j = foot_map[row & 3];
            const float* base = jp + ((size_t)(b * J_DIM + j) * 3) * T_DIM;
            const float* xr = base;
            const float* yr = base + T_DIM;
            const float* zr = base + 2 * T_DIM;

            int col = c4 * 4;
            float4 x = ((const float4*)xr)[c4];
            float4 y = ((const float4*)yr)[c4];
            float4 z = ((const float4*)zr)[c4];
            bool has_next = (col + 4 < T_DIM);
            float xs[5] = {x.x, x.y, x.z, x.w, has_next ? xr[col + 4] : 0.0f};
            float ys[5] = {y.x, y.y, y.z, y.w, has_next ? yr[col + 4] : 0.0f};
            float zs[5] = {z.x, z.y, z.z, z.w, has_next ? zr[col + 4] : 0.0f};

            int kmax = has_next ? 4 : 3;
            #pragma unroll
            for (int k = 0; k < 4; k++) {
                if (k < kmax) {
                    float w0 = sigmoidf_fast((CONTACT_THRESH - ys[k])     * 20.0f);
                    float w1 = sigmoidf_fast((CONTACT_THRESH - ys[k + 1]) * 20.0f);
                    float cw = 0.5f * (w0 + w1);
                    float dx = xs[k + 1] - xs[k];
                    float dz = zs[k + 1] - zs[k];
                    lsum += (dx * dx + dz * dz) * cw;
                    csum += cw;
                }
            }
        }
    }

    // ---------------- block reduction (R8 tail, measured best) ----------------
    __shared__ float s[4][8];
    #pragma unroll
    for (int o = 16; o; o >>= 1) {
        recon += __shfl_down_sync(0xFFFFFFFFu, recon, o);
        vel   += __shfl_down_sync(0xFFFFFFFFu, vel, o);
        lsum  += __shfl_down_sync(0xFFFFFFFFu, lsum, o);
        csum  += __shfl_down_sync(0xFFFFFFFFu, csum, o);
    }
    int warp = threadIdx.x >> 5;
    if ((threadIdx.x & 31) == 0) {
        s[0][warp] = recon; s[1][warp] = vel; s[2][warp] = lsum; s[3][warp] = csum;
    }
    __syncthreads();

    if (threadIdx.x < 4) {
        float sum = 0.0f;
        #pragma unroll
        for (int w = 0; w < NTHREADS / 32; w++) sum += s[threadIdx.x][w];
        atomicAdd(&g_acc[threadIdx.x], (double)sum);
        __threadfence();
    }
    __syncthreads();

    if (threadIdx.x == 0) {
        unsigned int done = atomicAdd(&g_done, 1u);
        if (done == gridDim.x - 1) {
            const double N1 = (double)B_DIM * J_DIM * 6 * T_DIM;
            const double N2 = (double)B_DIM * J_DIM * 6 * (T_DIM - 1);
            double recon_m = g_acc[0] / N1;
            double vel_m   = g_acc[1] / N2;
            double foot_m  = g_acc[2] / (g_acc[3] + 1e-08);
            out[0] = (float)(recon_m + LAMBDA_VEL * vel_m + LAMBDA_FOOT * foot_m);
            g_acc[0] = 0.0; g_acc[1] = 0.0; g_acc[2] = 0.0; g_acc[3] = 0.0;
            g_done = 0u;
        }
    }
}

extern "C" void kernel_launch(void* const* d_in, const int* in_sizes, int n_in,
                              void* d_out, int out_size) {
    const float* pred   = (const float*)d_in[0];
    const float* target = (const float*)d_in[1];
    const float* jp     = (const float*)d_in[2];
    float* out = (float*)d_out;
    k_fused<<<GRID_BLOCKS, NTHREADS>>>(pred, target, jp, out);
}